// round 1
// baseline (speedup 1.0000x reference)
#include <cuda_runtime.h>
#include <cstdint>

#define Zdim 41
#define Ydim 1024
#define Xdim 1024
#define NVOX (Zdim * Ydim * Xdim)   // 42,991,616
#define C_IN 32
#define C_OUT 64
#define KVOL 27

// Dense coordinate hash: grid[lin] = point_index + 1, 0 = empty.
// Zero-initialized at module load; we restore zeros at the end of every
// kernel_launch so graph replays are deterministic.
__device__ int g_grid[NVOX];

__global__ void scatter_kernel(const int* __restrict__ idx, int n) {
    int i = blockIdx.x * blockDim.x + threadIdx.x;
    if (i >= n) return;
    int z = idx[i * 4 + 1];
    int y = idx[i * 4 + 2];
    int x = idx[i * 4 + 3];
    size_t lin = (size_t)z * (Ydim * Xdim) + (size_t)y * Xdim + (size_t)x;
    g_grid[lin] = i + 1;
}

__global__ void clear_kernel(const int* __restrict__ idx, int n) {
    int i = blockIdx.x * blockDim.x + threadIdx.x;
    if (i >= n) return;
    int z = idx[i * 4 + 1];
    int y = idx[i * 4 + 2];
    int x = idx[i * 4 + 3];
    size_t lin = (size_t)z * (Ydim * Xdim) + (size_t)y * Xdim + (size_t)x;
    g_grid[lin] = 0;
}

// One warp per output point.
// Lanes 0..26 probe the 27 neighbor offsets in parallel (high MLP on the
// random grid lookups). For each active offset: coalesced feature-row
// gather (lane = cin), then a 32-step shuffle broadcast of the feature
// values; each lane accumulates cout = lane and cout = lane + 32.
__global__ void __launch_bounds__(256) conv_kernel(
    const float* __restrict__ feat,
    const int*   __restrict__ idx,
    const float* __restrict__ w,
    float* __restrict__ out,
    int n)
{
    int warp_global = (blockIdx.x * blockDim.x + threadIdx.x) >> 5;
    int lane = threadIdx.x & 31;
    if (warp_global >= n) return;
    int i = warp_global;

    int z = idx[i * 4 + 1];
    int y = idx[i * 4 + 2];
    int x = idx[i * 4 + 3];

    int nb = -1;
    if (lane < KVOL) {
        int dz = lane / 9 - 1;
        int dy = (lane / 3) % 3 - 1;
        int dx = lane % 3 - 1;
        int nz = z + dz, ny = y + dy, nx = x + dx;
        if ((unsigned)nz < Zdim && (unsigned)ny < Ydim && (unsigned)nx < Xdim) {
            size_t lin = (size_t)nz * (Ydim * Xdim) + (size_t)ny * Xdim + (size_t)nx;
            nb = g_grid[lin] - 1;   // -1 if empty
        }
    }

    unsigned act = __ballot_sync(0xffffffffu, nb >= 0);

    float acc0 = 0.0f, acc1 = 0.0f;

    while (act) {
        int k = __ffs(act) - 1;
        act &= act - 1;
        int j = __shfl_sync(0xffffffffu, nb, k);

        // Coalesced gather of the neighbor's feature row (128 B).
        float f = feat[(size_t)j * C_IN + lane];

        const float* wk = w + (size_t)k * C_IN * C_OUT;
        #pragma unroll
        for (int c = 0; c < C_IN; ++c) {
            float fv = __shfl_sync(0xffffffffu, f, c);
            acc0 += fv * wk[c * C_OUT + lane];
            acc1 += fv * wk[c * C_OUT + lane + 32];
        }
    }

    out[(size_t)i * C_OUT + lane]      = acc0;
    out[(size_t)i * C_OUT + lane + 32] = acc1;
}

extern "C" void kernel_launch(void* const* d_in, const int* in_sizes, int n_in,
                              void* d_out, int out_size) {
    const float* feat = (const float*)d_in[0];
    const int*   idx  = (const int*)d_in[1];
    const float* w    = (const float*)d_in[2];
    float* out = (float*)d_out;

    int n = in_sizes[0] / C_IN;   // N points

    int threads = 256;
    int blocks_pts = (n + threads - 1) / threads;

    scatter_kernel<<<blocks_pts, threads>>>(idx, n);

    // one warp per point -> 8 points per 256-thread block
    int blocks_conv = (n + 7) / 8;
    conv_kernel<<<blocks_conv, threads>>>(feat, idx, w, out, n);

    clear_kernel<<<blocks_pts, threads>>>(idx, n);
}